// round 15
// baseline (speedup 1.0000x reference)
#include <cuda_runtime.h>
#include <cuda_fp16.h>
#include <math.h>

typedef unsigned long long ull;

#define NN   100000
#define EE   1600000
#define INC  128
#define HID  64
#define NCLS 40

#define SCAN_B 512
#define NB_SCAN ((NN + SCAN_B - 1) / SCAN_B)   // 196

// ---------------- device scratch ----------------
__device__ int      g_is64;
__device__ int      g_deg[NN];
__device__ float    g_dis[NN];
__device__ int      g_off[NN + 1];
__device__ int      g_pos[NN];
__device__ int      g_srcs[EE];
__device__ unsigned g_pub[NB_SCAN];
__device__ __half   g_hh[(size_t)NN * HID];    // fp16 dis-scaled x@W1 (128B rows)
__device__ float    g_h2[(size_t)NN * HID];    // relu(agg1 + b1), fp32
__device__ __half   g_gh[(size_t)NN * NCLS];   // fp16 dis-scaled h2@W2 (80B rows)

// ---------------- f32x2 helpers ----------------
__device__ __forceinline__ ull splat2(float a) {
    ull r; asm("mov.b64 %0, {%1, %1};" : "=l"(r) : "f"(a)); return r;
}
__device__ __forceinline__ ull fma2(ull a, ull b, ull c) {
    asm("fma.rn.f32x2 %0, %1, %2, %0;" : "+l"(c) : "l"(a), "l"(b)); return c;
}
__device__ __forceinline__ float2 up2(ull v) {
    float2 f; asm("mov.b64 {%0, %1}, %2;" : "=f"(f.x), "=f"(f.y) : "l"(v)); return f;
}

// ---------------- init: zero deg, reset scan state, dtype probe ----------------
__global__ void k_init(const int* __restrict__ e32) {
    int i = blockIdx.x * blockDim.x + threadIdx.x;
    if (i < NN) g_deg[i] = 0;
    if (i < NB_SCAN) g_pub[i] = 0u;
    if (i == 0) {
        int all0 = 1;
        for (int j = 0; j < 64; j++)
            if (e32[2 * j + 1] != 0) { all0 = 0; break; }
        g_is64 = all0;
    }
}

// ---------------- count: 8 edges per thread ----------------
__global__ void k_count(const void* __restrict__ eidx) {
    int t = blockIdx.x * blockDim.x + threadIdx.x;
    if (t >= EE / 8) return;
    int d[8];
    if (g_is64) {
        const longlong2* p = (const longlong2*)eidx + (size_t)EE / 2 + (size_t)t * 4;
        #pragma unroll
        for (int j = 0; j < 4; j++) {
            longlong2 a = p[j];
            d[2 * j] = (int)a.x; d[2 * j + 1] = (int)a.y;
        }
    } else {
        const int4* p = (const int4*)eidx + (size_t)EE / 4 + (size_t)t * 2;
        int4 a = p[0], b = p[1];
        d[0] = a.x; d[1] = a.y; d[2] = a.z; d[3] = a.w;
        d[4] = b.x; d[5] = b.y; d[6] = b.z; d[7] = b.w;
    }
    #pragma unroll
    for (int j = 0; j < 8; j++)
        if ((unsigned)d[j] < NN) atomicAdd(&g_deg[d[j]], 1);
}

// ---------------- single-pass scan with decoupled lookback ----------------
__global__ __launch_bounds__(SCAN_B) void k_scan() {
    __shared__ int s[SCAN_B];
    int tid = threadIdx.x;
    int b = blockIdx.x;
    int i = b * SCAN_B + tid;
    int v = (i < NN) ? g_deg[i] : 0;
    s[tid] = v;
    __syncthreads();
    for (int o = 1; o < SCAN_B; o <<= 1) {
        int t = 0;
        if (tid >= o) t = s[tid - o];
        __syncthreads();
        s[tid] += t;
        __syncthreads();
    }
    int incl = s[tid];

    if (tid == SCAN_B - 1)
        atomicExch(&g_pub[b], 0x80000000u | (unsigned)incl);

    int pre = 0;
    if (tid < b) {
        unsigned u;
        do { u = atomicAdd(&g_pub[tid], 0u); } while (!(u & 0x80000000u));
        pre = (int)(u & 0x7fffffffu);
    }
    __syncthreads();
    s[tid] = pre;
    __syncthreads();
    #pragma unroll
    for (int o = SCAN_B / 2; o > 0; o >>= 1) {
        if (tid < o) s[tid] += s[tid + o];
        __syncthreads();
    }
    int blockoff = s[0];

    if (i < NN) {
        int o = blockoff + incl - v;
        g_off[i] = o;
        g_pos[i] = o;
        g_dis[i] = rsqrtf((float)(v + 1));
    }
    if (b == 0 && tid == 0) g_off[NN] = EE;
}

// ---------------- fill: 8 edges per thread ----------------
__global__ void k_fill(const void* __restrict__ eidx) {
    int t = blockIdx.x * blockDim.x + threadIdx.x;
    if (t >= EE / 8) return;
    int sv[8], dv[8];
    if (g_is64) {
        const longlong2* ps = (const longlong2*)eidx + (size_t)t * 4;
        const longlong2* pd = (const longlong2*)eidx + (size_t)EE / 2 + (size_t)t * 4;
        #pragma unroll
        for (int j = 0; j < 4; j++) {
            longlong2 a = ps[j], c = pd[j];
            sv[2 * j] = (int)a.x; sv[2 * j + 1] = (int)a.y;
            dv[2 * j] = (int)c.x; dv[2 * j + 1] = (int)c.y;
        }
    } else {
        const int4* ps = (const int4*)eidx + (size_t)t * 2;
        const int4* pd = (const int4*)eidx + (size_t)EE / 4 + (size_t)t * 2;
        int4 a = ps[0], b = ps[1], c = pd[0], d = pd[1];
        sv[0] = a.x; sv[1] = a.y; sv[2] = a.z; sv[3] = a.w;
        sv[4] = b.x; sv[5] = b.y; sv[6] = b.z; sv[7] = b.w;
        dv[0] = c.x; dv[1] = c.y; dv[2] = c.z; dv[3] = c.w;
        dv[4] = d.x; dv[5] = d.y; dv[6] = d.z; dv[7] = d.w;
    }
    int p[8];
    #pragma unroll
    for (int j = 0; j < 8; j++) {
        p[j] = -1;
        if ((unsigned)dv[j] < NN && (unsigned)sv[j] < NN)
            p[j] = atomicAdd(&g_pos[dv[j]], 1);
    }
    #pragma unroll
    for (int j = 0; j < 8; j++)
        if ((unsigned)p[j] < EE) g_srcs[p[j]] = sv[j];
}

// ---------------- GEMM1 (HMMA): g_hh = fp16(dis * (x @ W1)) ----------------
// block = 128 thr (4 warps); tile = 64 rows x 64 cols x K=128.
// x and W1^T staged as fp16 in smem (stride 136 halves, conflict-free frag loads).
// Each warp: 16 rows, 8 n-tiles x 8 k-steps of mma.m16n8k16.
// dis from g_deg (forked after k_count; no device-side sync).
#define ASTR 136
__global__ __launch_bounds__(128) void k_gemm1(const float* __restrict__ x,
                                               const float* __restrict__ W1) {
    __shared__ __half sA[64 * ASTR];    // x tile   [row][k]
    __shared__ __half sB[64 * ASTR];    // W1^T     [n][k]
    int tid = threadIdx.x;
    int row0 = blockIdx.x * 64;

    // stage x tile: 2048 float4 (64 rows x 32 f4), convert to fp16
    {
        const float4* xg = (const float4*)x;
        for (int idx = tid; idx < 2048; idx += 128) {
            int r = idx >> 5, q = idx & 31;
            int gr = row0 + r; if (gr >= NN) gr = 0;     // clamp (stores guarded)
            float4 v = xg[(size_t)gr * 32 + q];
            __half2* dst = (__half2*)&sA[r * ASTR + q * 4];
            dst[0] = __floats2half2_rn(v.x, v.y);
            dst[1] = __floats2half2_rn(v.z, v.w);
        }
    }
    // stage W1^T: W1 is [k=128][n=64] fp32 -> sB[n][k] fp16
    {
        const float4* wg = (const float4*)W1;
        for (int idx = tid; idx < 2048; idx += 128) {
            int k = idx >> 4, n0 = (idx & 15) * 4;
            float4 v = wg[idx];
            sB[(n0 + 0) * ASTR + k] = __float2half_rn(v.x);
            sB[(n0 + 1) * ASTR + k] = __float2half_rn(v.y);
            sB[(n0 + 2) * ASTR + k] = __float2half_rn(v.z);
            sB[(n0 + 3) * ASTR + k] = __float2half_rn(v.w);
        }
    }
    __syncthreads();

    int w = tid >> 5;                   // warp 0..3 -> rows w*16..w*16+15
    int lane = tid & 31;
    int g = lane >> 2;                  // 0..7
    int t = lane & 3;                   // 0..3
    int m0 = w * 16;

    float acc[8][4];
    #pragma unroll
    for (int j = 0; j < 8; j++)
        #pragma unroll
        for (int q = 0; q < 4; q++) acc[j][q] = 0.f;

    #pragma unroll 1
    for (int k0 = 0; k0 < 8; k0++) {
        int kb = k0 * 16;
        unsigned a0 = *(unsigned*)&sA[(m0 + g)     * ASTR + kb + 2 * t];
        unsigned a1 = *(unsigned*)&sA[(m0 + g + 8) * ASTR + kb + 2 * t];
        unsigned a2 = *(unsigned*)&sA[(m0 + g)     * ASTR + kb + 8 + 2 * t];
        unsigned a3 = *(unsigned*)&sA[(m0 + g + 8) * ASTR + kb + 8 + 2 * t];
        #pragma unroll
        for (int j = 0; j < 8; j++) {
            unsigned b0 = *(unsigned*)&sB[(j * 8 + g) * ASTR + kb + 2 * t];
            unsigned b1 = *(unsigned*)&sB[(j * 8 + g) * ASTR + kb + 8 + 2 * t];
            asm volatile(
                "mma.sync.aligned.m16n8k16.row.col.f32.f16.f16.f32 "
                "{%0,%1,%2,%3}, {%4,%5,%6,%7}, {%8,%9}, {%0,%1,%2,%3};"
                : "+f"(acc[j][0]), "+f"(acc[j][1]), "+f"(acc[j][2]), "+f"(acc[j][3])
                : "r"(a0), "r"(a1), "r"(a2), "r"(a3), "r"(b0), "r"(b1));
        }
    }

    // epilogue: D[g][2t..2t+1] = acc[j][0..1], D[g+8][2t..2t+1] = acc[j][2..3]
    int rowA = row0 + m0 + g;
    int rowB = rowA + 8;
    bool okA = rowA < NN, okB = rowB < NN;
    float dA = okA ? rsqrtf((float)(g_deg[rowA] + 1)) : 0.f;
    float dB = okB ? rsqrtf((float)(g_deg[rowB] + 1)) : 0.f;
    #pragma unroll
    for (int j = 0; j < 8; j++) {
        int col = j * 8 + 2 * t;
        if (okA) {
            __half2 h = __floats2half2_rn(acc[j][0] * dA, acc[j][1] * dA);
            *(unsigned*)&g_hh[(size_t)rowA * HID + col] = *(unsigned*)&h;
        }
        if (okB) {
            __half2 h = __floats2half2_rn(acc[j][2] * dB, acc[j][3] * dB);
            *(unsigned*)&g_hh[(size_t)rowB * HID + col] = *(unsigned*)&h;
        }
    }
}

// ---------------- Agg1: 4 edge-groups/warp, 3-deep pipelined uint4 gathers (R9) ----------------
__global__ __launch_bounds__(256) void k_agg1(const float* __restrict__ b1) {
    int gwarp = (blockIdx.x * blockDim.x + threadIdx.x) >> 5;
    if (gwarp >= NN) return;
    int node = gwarp;
    int lane = threadIdx.x & 31;
    int grp = lane >> 3;
    int l8  = lane & 7;

    const uint4* hh = (const uint4*)g_hh;
    float acc[8];
    #pragma unroll
    for (int j = 0; j < 8; j++) acc[j] = 0.f;

    if (grp == 0) {                    // self term (prescaled)
        uint4 v = hh[(size_t)node * 8 + l8];
        float2 f;
        f = __half22float2(*(__half2*)&v.x); acc[0] = f.x; acc[1] = f.y;
        f = __half22float2(*(__half2*)&v.y); acc[2] = f.x; acc[3] = f.y;
        f = __half22float2(*(__half2*)&v.z); acc[4] = f.x; acc[5] = f.y;
        f = __half22float2(*(__half2*)&v.w); acc[6] = f.x; acc[7] = f.y;
    }

    int beg = g_off[node], end = g_off[node + 1];
    int e = beg + grp;
    bool hA = e < end;
    bool hB = e + 4 < end;
    bool hC = e + 8 < end;
    int sA = hA ? g_srcs[e] : 0;
    int sB = hB ? g_srcs[e + 4] : 0;
    int sC = hC ? g_srcs[e + 8] : 0;

    while (hA) {
        int en = e + 12;
        bool hA2 = en < end, hB2 = en + 4 < end, hC2 = en + 8 < end;
        int sA2 = hA2 ? g_srcs[en] : 0;
        int sB2 = hB2 ? g_srcs[en + 4] : 0;
        int sC2 = hC2 ? g_srcs[en + 8] : 0;

        uint4 vA = hh[(size_t)sA * 8 + l8];
        uint4 vB = hB ? hh[(size_t)sB * 8 + l8] : make_uint4(0u, 0u, 0u, 0u);
        uint4 vC = hC ? hh[(size_t)sC * 8 + l8] : make_uint4(0u, 0u, 0u, 0u);

        float2 f;
        f = __half22float2(*(__half2*)&vA.x); acc[0] += f.x; acc[1] += f.y;
        f = __half22float2(*(__half2*)&vA.y); acc[2] += f.x; acc[3] += f.y;
        f = __half22float2(*(__half2*)&vA.z); acc[4] += f.x; acc[5] += f.y;
        f = __half22float2(*(__half2*)&vA.w); acc[6] += f.x; acc[7] += f.y;
        f = __half22float2(*(__half2*)&vB.x); acc[0] += f.x; acc[1] += f.y;
        f = __half22float2(*(__half2*)&vB.y); acc[2] += f.x; acc[3] += f.y;
        f = __half22float2(*(__half2*)&vB.z); acc[4] += f.x; acc[5] += f.y;
        f = __half22float2(*(__half2*)&vB.w); acc[6] += f.x; acc[7] += f.y;
        f = __half22float2(*(__half2*)&vC.x); acc[0] += f.x; acc[1] += f.y;
        f = __half22float2(*(__half2*)&vC.y); acc[2] += f.x; acc[3] += f.y;
        f = __half22float2(*(__half2*)&vC.z); acc[4] += f.x; acc[5] += f.y;
        f = __half22float2(*(__half2*)&vC.w); acc[6] += f.x; acc[7] += f.y;

        hA = hA2; hB = hB2; hC = hC2; sA = sA2; sB = sB2; sC = sC2; e = en;
    }

    #pragma unroll
    for (int j = 0; j < 8; j++)
        acc[j] += __shfl_down_sync(0xffffffffu, acc[j], 16);
    #pragma unroll
    for (int j = 0; j < 8; j++)
        acc[j] += __shfl_down_sync(0xffffffffu, acc[j], 8);

    if (grp == 0) {
        float di = g_dis[node];
        float4 b0 = ((const float4*)b1)[l8 * 2];
        float4 b4 = ((const float4*)b1)[l8 * 2 + 1];
        float4* o = (float4*)(g_h2 + (size_t)node * HID + l8 * 8);
        o[0] = make_float4(fmaxf(fmaf(di, acc[0], b0.x), 0.f),
                           fmaxf(fmaf(di, acc[1], b0.y), 0.f),
                           fmaxf(fmaf(di, acc[2], b0.z), 0.f),
                           fmaxf(fmaf(di, acc[3], b0.w), 0.f));
        o[1] = make_float4(fmaxf(fmaf(di, acc[4], b4.x), 0.f),
                           fmaxf(fmaf(di, acc[5], b4.y), 0.f),
                           fmaxf(fmaf(di, acc[6], b4.z), 0.f),
                           fmaxf(fmaf(di, acc[7], b4.w), 0.f));
    }
}

// ---------------- GEMM2: g_gh = fp16(dis * (h2 @ W2)), 8x10 register tile (R9) ----------------
__global__ __launch_bounds__(128) void k_gemm2(const float* __restrict__ W2) {
    __shared__ ull ws[HID * 20];          // 10 KB
    int tid = threadIdx.x;
    {
        const ulonglong2* w16 = (const ulonglong2*)W2;
        ulonglong2* wd = (ulonglong2*)ws;
        #pragma unroll
        for (int j = tid; j < HID * NCLS / 4; j += 128) wd[j] = w16[j];
    }
    __syncthreads();

    int colg = tid & 3;
    int rowg = tid >> 2;
    int row0 = blockIdx.x * 256 + rowg * 8;

    bool ok[8];
    const float4* hr[8];
    #pragma unroll
    for (int i = 0; i < 8; i++) {
        ok[i] = (row0 + i) < NN;
        hr[i] = (const float4*)(g_h2 + (size_t)(ok[i] ? row0 + i : 0) * HID);
    }

    ull acc[8][5];
    #pragma unroll
    for (int i = 0; i < 8; i++)
        #pragma unroll
        for (int j = 0; j < 5; j++) acc[i][j] = 0ULL;

    #pragma unroll 2
    for (int kc = 0; kc < 16; kc++) {
        float4 a4[8];
        #pragma unroll
        for (int i = 0; i < 8; i++) a4[i] = hr[i][kc];
        #pragma unroll
        for (int kk = 0; kk < 4; kk++) {
            int k = kc * 4 + kk;
            ull b[5];
            #pragma unroll
            for (int j = 0; j < 5; j++) b[j] = ws[k * 20 + colg * 5 + j];
            #pragma unroll
            for (int i = 0; i < 8; i++) {
                ull as = splat2(((const float*)&a4[i])[kk]);
                #pragma unroll
                for (int j = 0; j < 5; j++)
                    acc[i][j] = fma2(as, b[j], acc[i][j]);
            }
        }
    }

    #pragma unroll
    for (int i = 0; i < 8; i++) {
        if (!ok[i]) continue;
        float di = g_dis[row0 + i];
        unsigned* dst = (unsigned*)(g_gh + (size_t)(row0 + i) * NCLS + colg * 10);
        #pragma unroll
        for (int j = 0; j < 5; j++) {
            float2 f = up2(acc[i][j]);
            __half2 h = __floats2half2_rn(f.x * di, f.y * di);
            dst[j] = *(unsigned*)&h;
        }
    }
}

// ---------------- Agg2: 3 edge-groups/warp, 3-deep pipelined uint2 gathers (R9) ----------------
__global__ __launch_bounds__(256) void k_agg2(const float* __restrict__ b2,
                                              float* __restrict__ out) {
    int gwarp = (blockIdx.x * blockDim.x + threadIdx.x) >> 5;
    if (gwarp >= NN) return;
    int node = gwarp;
    int lane = threadIdx.x & 31;
    int grp = lane / 10;
    int li  = lane - grp * 10;

    const uint2* gg = (const uint2*)g_gh;   // 10 uint2 per row
    float acc[4] = {0.f, 0.f, 0.f, 0.f};

    if (grp == 0) {
        uint2 v = gg[(size_t)node * 10 + li];
        float2 f;
        f = __half22float2(*(__half2*)&v.x); acc[0] = f.x; acc[1] = f.y;
        f = __half22float2(*(__half2*)&v.y); acc[2] = f.x; acc[3] = f.y;
    }

    int beg = g_off[node], end = g_off[node + 1];
    if (grp < 3) {
        int e = beg + grp;
        bool hA = e < end;
        bool hB = e + 3 < end;
        bool hC = e + 6 < end;
        int sA = hA ? g_srcs[e] : 0;
        int sB = hB ? g_srcs[e + 3] : 0;
        int sC = hC ? g_srcs[e + 6] : 0;

        while (hA) {
            int en = e + 9;
            bool hA2 = en < end, hB2 = en + 3 < end, hC2 = en + 6 < end;
            int sA2 = hA2 ? g_srcs[en] : 0;
            int sB2 = hB2 ? g_srcs[en + 3] : 0;
            int sC2 = hC2 ? g_srcs[en + 6] : 0;

            uint2 vA = gg[(size_t)sA * 10 + li];
            uint2 vB = hB ? gg[(size_t)sB * 10 + li] : make_uint2(0u, 0u);
            uint2 vC = hC ? gg[(size_t)sC * 10 + li] : make_uint2(0u, 0u);

            float2 f;
            f = __half22float2(*(__half2*)&vA.x); acc[0] += f.x; acc[1] += f.y;
            f = __half22float2(*(__half2*)&vA.y); acc[2] += f.x; acc[3] += f.y;
            f = __half22float2(*(__half2*)&vB.x); acc[0] += f.x; acc[1] += f.y;
            f = __half22float2(*(__half2*)&vB.y); acc[2] += f.x; acc[3] += f.y;
            f = __half22float2(*(__half2*)&vC.x); acc[0] += f.x; acc[1] += f.y;
            f = __half22float2(*(__half2*)&vC.y); acc[2] += f.x; acc[3] += f.y;

            hA = hA2; hB = hB2; hC = hC2; sA = sA2; sB = sB2; sC = sC2; e = en;
        }
    }

    #pragma unroll
    for (int j = 0; j < 4; j++) {
        float t1 = __shfl_down_sync(0xffffffffu, acc[j], 10);
        float t2 = __shfl_down_sync(0xffffffffu, acc[j], 20);
        acc[j] += t1 + t2;
    }

    if (grp == 0) {
        float di = g_dis[node];
        float4 b = ((const float4*)b2)[li];
        float4 r;
        r.x = fmaf(di, acc[0], b.x);
        r.y = fmaf(di, acc[1], b.y);
        r.z = fmaf(di, acc[2], b.z);
        r.w = fmaf(di, acc[3], b.w);
        ((float4*)out)[(size_t)node * 10 + li] = r;
    }
}

// ---------------- launch (R9 structure) ----------------
extern "C" void kernel_launch(void* const* d_in, const int* in_sizes, int n_in,
                              void* d_out, int out_size) {
    const float* x    = (const float*)d_in[0];
    const void*  eidx = d_in[1];
    const float* W1   = (const float*)d_in[2];
    const float* b1   = (const float*)d_in[3];
    const float* W2   = (const float*)d_in[4];
    const float* b2   = (const float*)d_in[5];
    float* out = (float*)d_out;

    static cudaStream_t s2 = nullptr;
    static cudaEvent_t evD = nullptr, evG = nullptr;
    static bool use2 = false;
    if (!s2) {
        use2 = (cudaStreamCreateWithFlags(&s2, cudaStreamNonBlocking) == cudaSuccess) &&
               (cudaEventCreateWithFlags(&evD, cudaEventDisableTiming) == cudaSuccess) &&
               (cudaEventCreateWithFlags(&evG, cudaEventDisableTiming) == cudaSuccess);
        if (!use2) s2 = (cudaStream_t)0x1;
    }

    k_init<<<(NN + 255) / 256, 256>>>((const int*)eidx);
    k_count<<<(EE / 8 + 255) / 256, 256>>>(eidx);        // deg ready here

    if (use2) {
        cudaEventRecord(evD, 0);
        cudaStreamWaitEvent(s2, evD, 0);
        k_gemm1<<<(NN + 63) / 64, 128, 0, s2>>>(x, W1);   // ∥ scan+fill
        cudaEventRecord(evG, s2);

        k_scan<<<NB_SCAN, SCAN_B>>>();
        k_fill<<<(EE / 8 + 255) / 256, 256>>>(eidx);

        cudaStreamWaitEvent(0, evG, 0);
    } else {
        k_scan<<<NB_SCAN, SCAN_B>>>();
        k_gemm1<<<(NN + 63) / 64, 128>>>(x, W1);
        k_fill<<<(EE / 8 + 255) / 256, 256>>>(eidx);
    }

    k_agg1<<<NN / 8, 256>>>(b1);
    k_gemm2<<<(NN + 255) / 256, 128>>>(W2);
    k_agg2<<<NN / 8, 256>>>(b2, out);
}